// round 16
// baseline (speedup 1.0000x reference)
#include <cuda_runtime.h>
#include <cuda_fp16.h>
#include <math.h>
#include <stdint.h>

// Problem constants
#define BATCH 8
#define LSEQ  2048
#define DMODEL 512
#define NHEAD 8
#define NPNT  4
#define CHEAD 64
#define MROWS (BATCH * LSEQ)   // 16384
#define MHALF (MROWS / 2)      // 8192

// Scratch (device globals; no allocation allowed)
__device__ __align__(16) __half g_v[MROWS * DMODEL];
__device__ __align__(16) __half g_mid[MROWS * DMODEL];
__device__ __align__(16) float  g_offaw[MROWS * 128];
__device__ __align__(16) __half g_wvt[DMODEL * DMODEL];
__device__ __align__(16) __half g_wot[DMODEL * DMODEL];
__device__ __align__(16) __half g_wqt_hi[128 * DMODEL];
__device__ __align__(16) __half g_wqt_lo[128 * DMODEL];
__device__ __align__(16) float  g_bq[128];

// Streams/events (created once at module load).
static cudaStream_t g_s1;
static cudaEvent_t g_ev0, g_ev1, g_ev2;
namespace {
struct StreamInit {
    StreamInit() {
        cudaStreamCreateWithFlags(&g_s1, cudaStreamNonBlocking);
        cudaEventCreateWithFlags(&g_ev0, cudaEventDisableTiming);
        cudaEventCreateWithFlags(&g_ev1, cudaEventDisableTiming);
        cudaEventCreateWithFlags(&g_ev2, cudaEventDisableTiming);
    }
};
StreamInit g_stream_init;
}

__device__ __forceinline__ uint32_t smem_u32(const void* p) {
    uint32_t a;
    asm("{ .reg .u64 t; cvta.to.shared.u64 t, %1; cvt.u32.u64 %0, t; }" : "=r"(a) : "l"(p));
    return a;
}

__device__ __forceinline__ void mma_f16(float c[4],
                                        const uint32_t a[4],
                                        uint32_t b0, uint32_t b1) {
    asm volatile(
        "mma.sync.aligned.m16n8k16.row.col.f32.f16.f16.f32 "
        "{%0,%1,%2,%3}, {%4,%5,%6,%7}, {%8,%9}, {%0,%1,%2,%3};"
        : "+f"(c[0]), "+f"(c[1]), "+f"(c[2]), "+f"(c[3])
        : "r"(a[0]), "r"(a[1]), "r"(a[2]), "r"(a[3]), "r"(b0), "r"(b1));
}

__device__ __forceinline__ void ldsm_x4(uint32_t r[4], uint32_t addr) {
    asm volatile(
        "ldmatrix.sync.aligned.m8n8.x4.shared.b16 {%0,%1,%2,%3}, [%4];"
        : "=r"(r[0]), "=r"(r[1]), "=r"(r[2]), "=r"(r[3]) : "r"(addr));
}

#define CP_ASYNC16(dst, src) \
    asm volatile("cp.async.cg.shared.global [%0], [%1], 16;" :: "r"(dst), "l"(src) : "memory")
#define CP_COMMIT() asm volatile("cp.async.commit_group;" ::: "memory")
#define CP_WAIT1()  asm volatile("cp.async.wait_group 1;" ::: "memory")
#define CP_WAIT2()  asm volatile("cp.async.wait_group 2;" ::: "memory")

// Common geometry
#define HG_KC 32
#define HG_ROWB 80

// 256x128 tile geometry (big GEMMs): A tile 256 rows, B tile 128 rows.
#define BG_AT (256 * HG_ROWB)            // 20480
#define BG_BT (128 * HG_ROWB)            // 10240
#define BG_STAGE (BG_AT + BG_BT)         // 30720
#define BG_STAGES 4
#define BG_SMEM (BG_STAGES * BG_STAGE)   // 122880

// offaw tile geometry (unchanged from r13-15)
#define FG_TILE (128 * HG_ROWB)
#define FG_STAGE (4 * FG_TILE)
#define FG_STAGES 3
#define FG_SMEM (FG_STAGES * FG_STAGE)   // 122880

// ===========================================================================
// out-GEMM, 256x128 tile, 512 threads: C[.,N] = A @ Bt^T + bias (fp32 out)
// ===========================================================================
template <typename OutT>
__global__ __launch_bounds__(512, 1)
void gemm_async_h256_kernel(const __half* __restrict__ A, const __half* __restrict__ Bt,
                            const float* __restrict__ bias, OutT* __restrict__ C,
                            int mbase, int N, int K)
{
    extern __shared__ char smem[];
    const uint32_t sbase = smem_u32(smem);

    const int tid  = threadIdx.x;
    const int wid  = tid >> 5;        // 0..15
    const int lane = tid & 31;
    const int g    = lane >> 2;
    const int tig  = lane & 3;
    const int wm   = wid & 7;         // 8 m-warps (32 rows each)
    const int wn   = wid >> 3;        // 2 n-warps (64 cols each)

    const int m0 = mbase + blockIdx.y * 256;
    const int n0 = blockIdx.x * 128;

    const uint32_t aOff = (uint32_t)((wm * 32 + (lane & 15)) * HG_ROWB + (lane >> 4) * 16);
    const uint32_t bOff = (uint32_t)(BG_AT +
        (wn * 64 + (lane & 7) + (lane >> 4) * 8) * HG_ROWB + ((lane >> 3) & 1) * 16);

    float acc[2][8][4];
#pragma unroll
    for (int mt = 0; mt < 2; mt++)
#pragma unroll
        for (int nt = 0; nt < 8; nt++)
#pragma unroll
            for (int j = 0; j < 4; j++) acc[mt][nt][j] = 0.0f;

    const int nch = K / HG_KC;

#define H2COPY_STAGE(s, chunk)                                                 \
    do {                                                                       \
        const int _k0 = (chunk) * HG_KC;                                       \
        const uint32_t _dA = sbase + (s) * BG_STAGE;                           \
        const uint32_t _dB = _dA + BG_AT;                                      \
        _Pragma("unroll")                                                      \
        for (int e = 0; e < 2; e++) {                                          \
            const int cc = tid + e * 512;      /* 0..1023 */                   \
            const int r = cc >> 2;             /* 0..255 */                    \
            const int q = cc & 3;                                              \
            CP_ASYNC16(_dA + r * HG_ROWB + q * 16,                             \
                       &A[(size_t)(m0 + r) * K + _k0 + q * 8]);                \
        }                                                                      \
        {                                                                      \
            const int r = tid >> 2;            /* 0..127 */                    \
            const int q = tid & 3;                                             \
            CP_ASYNC16(_dB + r * HG_ROWB + q * 16,                             \
                       &Bt[(size_t)(n0 + r) * K + _k0 + q * 8]);               \
        }                                                                      \
    } while (0)

    H2COPY_STAGE(0, 0); CP_COMMIT();
    H2COPY_STAGE(1, 1); CP_COMMIT();
    H2COPY_STAGE(2, 2); CP_COMMIT();

    for (int c = 0; c < nch; ++c) {
        CP_WAIT2();
        __syncthreads();

        if (c + 3 < nch) {
            H2COPY_STAGE((c + 3) % BG_STAGES, c + 3);
        }
        CP_COMMIT();

        const uint32_t stageBase = sbase + (c % BG_STAGES) * BG_STAGE;
        const uint32_t aBase = stageBase + aOff;
        const uint32_t bBase = stageBase + bOff;

#pragma unroll
        for (int ks = 0; ks < 2; ks++) {
            uint32_t a0[4], a1[4];
            ldsm_x4(a0, aBase + ks * 32);
            ldsm_x4(a1, aBase + 16 * HG_ROWB + ks * 32);
#pragma unroll
            for (int j = 0; j < 4; j++) {
                uint32_t b[4];
                ldsm_x4(b, bBase + j * 16 * HG_ROWB + ks * 32);
                mma_f16(acc[0][2 * j],     a0, b[0], b[1]);
                mma_f16(acc[1][2 * j],     a1, b[0], b[1]);
                mma_f16(acc[0][2 * j + 1], a0, b[2], b[3]);
                mma_f16(acc[1][2 * j + 1], a1, b[2], b[3]);
            }
        }
        __syncthreads();
    }
#undef H2COPY_STAGE

#pragma unroll
    for (int mt = 0; mt < 2; mt++) {
        const int row0 = m0 + wm * 32 + mt * 16 + g;
#pragma unroll
        for (int nt = 0; nt < 8; nt++) {
            const int col = n0 + wn * 64 + nt * 8 + tig * 2;
            const float bx = bias[col];
            const float by = bias[col + 1];
            const float l0 = acc[mt][nt][0] + bx;
            const float l1 = acc[mt][nt][1] + by;
            const float h0 = acc[mt][nt][2] + bx;
            const float h1 = acc[mt][nt][3] + by;
            if constexpr (sizeof(OutT) == 2) {
                __half2* p0 = reinterpret_cast<__half2*>(&C[(size_t)row0 * N + col]);
                __half2* p1 = reinterpret_cast<__half2*>(&C[(size_t)(row0 + 8) * N + col]);
                *p0 = __floats2half2_rn(l0, l1);
                *p1 = __floats2half2_rn(h0, h1);
            } else {
                float2 lo, hi;
                lo.x = l0; lo.y = l1; hi.x = h0; hi.y = h1;
                *reinterpret_cast<float2*>(&C[(size_t)row0 * N + col]) = lo;
                *reinterpret_cast<float2*>(&C[(size_t)(row0 + 8) * N + col]) = hi;
            }
        }
    }
}

// ===========================================================================
// v-GEMM, 256x128 tile, 512 threads, fused fp32->fp16 A conversion.
// ===========================================================================
__global__ __launch_bounds__(512, 1)
void gemm_v256_kernel(const float* __restrict__ A, const __half* __restrict__ Bt,
                      const float* __restrict__ bias, __half* __restrict__ C,
                      int mbase, int N, int K)
{
    extern __shared__ char smem[];
    const uint32_t sbase = smem_u32(smem);

    const int tid  = threadIdx.x;
    const int wid  = tid >> 5;
    const int lane = tid & 31;
    const int g    = lane >> 2;
    const int tig  = lane & 3;
    const int wm   = wid & 7;
    const int wn   = wid >> 3;

    const int m0 = mbase + blockIdx.y * 256;
    const int n0 = blockIdx.x * 128;

    const uint32_t aOff = (uint32_t)((wm * 32 + (lane & 15)) * HG_ROWB + (lane >> 4) * 16);
    const uint32_t bOff = (uint32_t)(BG_AT +
        (wn * 64 + (lane & 7) + (lane >> 4) * 8) * HG_ROWB + ((lane >> 3) & 1) * 16);

    float4 areg[2][2];

    float acc[2][8][4];
#pragma unroll
    for (int mt = 0; mt < 2; mt++)
#pragma unroll
        for (int nt = 0; nt < 8; nt++)
#pragma unroll
            for (int j = 0; j < 4; j++) acc[mt][nt][j] = 0.0f;

    const int nch = K / HG_KC;

#define V2_LDG_A(k0)                                                           \
    do {                                                                       \
        _Pragma("unroll")                                                      \
        for (int e = 0; e < 2; e++) {                                          \
            const int i = tid + e * 512;                                       \
            const int r = i >> 2;                                              \
            const int q2 = i & 3;                                              \
            const float* pA = &A[(size_t)(m0 + r) * K + (k0) + q2 * 8];        \
            areg[e][0] = *reinterpret_cast<const float4*>(pA);                 \
            areg[e][1] = *reinterpret_cast<const float4*>(pA + 4);             \
        }                                                                      \
    } while (0)

#define V2_STS_A(s)                                                            \
    do {                                                                       \
        _Pragma("unroll")                                                      \
        for (int e = 0; e < 2; e++) {                                          \
            const int i = tid + e * 512;                                       \
            const int r = i >> 2;                                              \
            const int q2 = i & 3;                                              \
            __half2 h0 = __floats2half2_rn(areg[e][0].x, areg[e][0].y);        \
            __half2 h1 = __floats2half2_rn(areg[e][0].z, areg[e][0].w);        \
            __half2 h2 = __floats2half2_rn(areg[e][1].x, areg[e][1].y);        \
            __half2 h3 = __floats2half2_rn(areg[e][1].z, areg[e][1].w);        \
            uint4 o;                                                           \
            o.x = *reinterpret_cast<uint32_t*>(&h0);                           \
            o.y = *reinterpret_cast<uint32_t*>(&h1);                           \
            o.z = *reinterpret_cast<uint32_t*>(&h2);                           \
            o.w = *reinterpret_cast<uint32_t*>(&h3);                           \
            *reinterpret_cast<uint4*>(                                         \
                smem + (s) * BG_STAGE + r * HG_ROWB + q2 * 16) = o;            \
        }                                                                      \
    } while (0)

#define V2_COPY_B(s, chunk)                                                    \
    do {                                                                       \
        const int _k0 = (chunk) * HG_KC;                                       \
        const uint32_t _dB = sbase + (s) * BG_STAGE + BG_AT;                   \
        const int r = tid >> 2;                                                \
        const int q = tid & 3;                                                 \
        CP_ASYNC16(_dB + r * HG_ROWB + q * 16,                                 \
                   &Bt[(size_t)(n0 + r) * K + _k0 + q * 8]);                   \
    } while (0)

    V2_LDG_A(0);          V2_STS_A(0);
    V2_LDG_A(HG_KC);      V2_STS_A(1);
    V2_LDG_A(2 * HG_KC);  V2_STS_A(2);
    V2_COPY_B(0, 0); CP_COMMIT();
    V2_COPY_B(1, 1); CP_COMMIT();
    V2_COPY_B(2, 2); CP_COMMIT();

    for (int c = 0; c < nch; ++c) {
        CP_WAIT2();
        __syncthreads();

        const bool pre = (c + 3) < nch;
        if (pre) {
            V2_LDG_A((c + 3) * HG_KC);
            V2_COPY_B((c + 3) % BG_STAGES, c + 3);
        }
        CP_COMMIT();

        const uint32_t stageBase = sbase + (c % BG_STAGES) * BG_STAGE;
        const uint32_t aBase = stageBase + aOff;
        const uint32_t bBase = stageBase + bOff;

#pragma unroll
        for (int ks = 0; ks < 2; ks++) {
            uint32_t a0[4], a1[4];
            ldsm_x4(a0, aBase + ks * 32);
            ldsm_x4(a1, aBase + 16 * HG_ROWB + ks * 32);
#pragma unroll
            for (int j = 0; j < 4; j++) {
                uint32_t b[4];
                ldsm_x4(b, bBase + j * 16 * HG_ROWB + ks * 32);
                mma_f16(acc[0][2 * j],     a0, b[0], b[1]);
                mma_f16(acc[1][2 * j],     a1, b[0], b[1]);
                mma_f16(acc[0][2 * j + 1], a0, b[2], b[3]);
                mma_f16(acc[1][2 * j + 1], a1, b[2], b[3]);
            }
        }

        if (pre) V2_STS_A((c + 3) % BG_STAGES);
        __syncthreads();
    }
#undef V2_LDG_A
#undef V2_STS_A
#undef V2_COPY_B

#pragma unroll
    for (int mt = 0; mt < 2; mt++) {
        const int row0 = m0 + wm * 32 + mt * 16 + g;
#pragma unroll
        for (int nt = 0; nt < 8; nt++) {
            const int col = n0 + wn * 64 + nt * 8 + tig * 2;
            const float bx = bias[col];
            const float by = bias[col + 1];
            __half2* p0 = reinterpret_cast<__half2*>(&C[(size_t)row0 * N + col]);
            __half2* p1 = reinterpret_cast<__half2*>(&C[(size_t)(row0 + 8) * N + col]);
            *p0 = __floats2half2_rn(acc[mt][nt][0] + bx, acc[mt][nt][1] + by);
            *p1 = __floats2half2_rn(acc[mt][nt][2] + bx, acc[mt][nt][3] + by);
        }
    }
}

// ===========================================================================
// Fused split-fp16 off/aw GEMM (in-kernel query split + ldmatrix) — unchanged.
// ===========================================================================
__global__ __launch_bounds__(256, 1)
void gemm_offaw_fused_kernel(const float* __restrict__ Q,
                             const __half* __restrict__ Bh, const __half* __restrict__ Bl,
                             const float* __restrict__ bias, float* __restrict__ C,
                             int mbase, int K)
{
    extern __shared__ char smem[];
    const uint32_t sbase = smem_u32(smem);
    const int N = 128;

    const int tid  = threadIdx.x;
    const int wid  = tid >> 5;
    const int lane = tid & 31;
    const int g    = lane >> 2;
    const int tig  = lane & 3;
    const int wm   = wid & 3;
    const int wn   = wid >> 2;

    const int m0 = mbase + blockIdx.y * 128;

    const uint32_t aOff = (uint32_t)((wm * 32 + (lane & 15)) * HG_ROWB + (lane >> 4) * 16);
    const uint32_t bOff = (uint32_t)(
        (wn * 64 + (lane & 7) + (lane >> 4) * 8) * HG_ROWB + ((lane >> 3) & 1) * 16);

    float4 areg[2][2];

    float acc[2][8][4];
#pragma unroll
    for (int mt = 0; mt < 2; mt++)
#pragma unroll
        for (int nt = 0; nt < 8; nt++)
#pragma unroll
            for (int j = 0; j < 4; j++) acc[mt][nt][j] = 0.0f;

    const int nch = K / HG_KC;

#define FO_LDG_A(k0)                                                           \
    do {                                                                       \
        _Pragma("unroll")                                                      \
        for (int e = 0; e < 2; e++) {                                          \
            const int i = tid + e * 256;                                       \
            const int r = i >> 2;                                              \
            const int q2 = i & 3;                                              \
            const float* pQ = &Q[(size_t)(m0 + r) * K + (k0) + q2 * 8];        \
            areg[e][0] = *reinterpret_cast<const float4*>(pQ);                 \
            areg[e][1] = *reinterpret_cast<const float4*>(pQ + 4);             \
        }                                                                      \
    } while (0)

#define FO_STS_A(s)                                                            \
    do {                                                                       \
        _Pragma("unroll")                                                      \
        for (int e = 0; e < 2; e++) {                                          \
            const int i = tid + e * 256;                                       \
            const int r = i >> 2;                                              \
            const int q2 = i & 3;                                              \
            const uint32_t od = (s) * FG_STAGE + r * HG_ROWB + q2 * 16;        \
            float hf[8], lf[8];                                                \
            const float* av = reinterpret_cast<const float*>(areg[e]);         \
            _Pragma("unroll")                                                  \
            for (int x = 0; x < 8; x++) {                                      \
                const __half hh = __float2half_rn(av[x]);                      \
                hf[x] = __half2float(hh);                                      \
                lf[x] = av[x] - hf[x];                                         \
            }                                                                  \
            __half2 H[4], L[4];                                                \
            _Pragma("unroll")                                                  \
            for (int x = 0; x < 4; x++) {                                      \
                H[x] = __floats2half2_rn(hf[2 * x], hf[2 * x + 1]);            \
                L[x] = __floats2half2_rn(lf[2 * x], lf[2 * x + 1]);            \
            }                                                                  \
            uint4 oh, ol;                                                      \
            oh.x = *reinterpret_cast<uint32_t*>(&H[0]);                        \
            oh.y = *reinterpret_cast<uint32_t*>(&H[1]);                        \
            oh.z = *reinterpret_cast<uint32_t*>(&H[2]);                        \
            oh.w = *reinterpret_cast<uint32_t*>(&H[3]);                        \
            ol.x = *reinterpret_cast<uint32_t*>(&L[0]);                        \
            ol.y = *reinterpret_cast<uint32_t*>(&L[1]);                        \
            ol.z = *reinterpret_cast<uint32_t*>(&L[2]);                        \
            ol.w = *reinterpret_cast<uint32_t*>(&L[3]);                        \
            *reinterpret_cast<uint4*>(smem + od) = oh;                         \
            *reinterpret_cast<uint4*>(smem + FG_TILE + od) = ol;               \
        }                                                                      \
    } while (0)

#define FO_COPY_B(s, chunk)                                                    \
    do {                                                                       \
        const int _k0 = (chunk) * HG_KC;                                       \
        const uint32_t _d0 = sbase + (s) * FG_STAGE;                           \
        _Pragma("unroll")                                                      \
        for (int e = 0; e < 2; e++) {                                          \
            const int cc = tid + e * 256;                                      \
            const int r = cc >> 2;                                             \
            const int q = cc & 3;                                              \
            const uint32_t od = r * HG_ROWB + q * 16;                          \
            const size_t ob = (size_t)r * K + _k0 + q * 8;                     \
            CP_ASYNC16(_d0 + 2 * FG_TILE + od, &Bh[ob]);                       \
            CP_ASYNC16(_d0 + 3 * FG_TILE + od, &Bl[ob]);                       \
        }                                                                      \
    } while (0)

    FO_LDG_A(0);      FO_STS_A(0);
    FO_LDG_A(HG_KC);  FO_STS_A(1);
    FO_COPY_B(0, 0); CP_COMMIT();
    FO_COPY_B(1, 1); CP_COMMIT();

    for (int c = 0; c < nch; ++c) {
        CP_WAIT1();
        __syncthreads();

        const bool pre = (c + 2) < nch;
        if (pre) {
            FO_LDG_A((c + 2) * HG_KC);
            FO_COPY_B((c + 2) % FG_STAGES, c + 2);
        }
        CP_COMMIT();

        const uint32_t stageBase = sbase + (c % FG_STAGES) * FG_STAGE;
        const uint32_t ahBase = stageBase + aOff;
        const uint32_t alBase = ahBase + FG_TILE;
        const uint32_t bhBase = stageBase + 2 * FG_TILE + bOff;
        const uint32_t blBase = bhBase + FG_TILE;

#pragma unroll
        for (int ks = 0; ks < 2; ks++) {
            uint32_t ah0[4], ah1[4], al0[4], al1[4];
            ldsm_x4(ah0, ahBase + ks * 32);
            ldsm_x4(ah1, ahBase + 16 * HG_ROWB + ks * 32);
            ldsm_x4(al0, alBase + ks * 32);
            ldsm_x4(al1, alBase + 16 * HG_ROWB + ks * 32);
#pragma unroll
            for (int j = 0; j < 4; j++) {
                uint32_t bh[4], bl[4];
                ldsm_x4(bh, bhBase + j * 16 * HG_ROWB + ks * 32);
                ldsm_x4(bl, blBase + j * 16 * HG_ROWB + ks * 32);
                mma_f16(acc[0][2 * j],     ah0, bh[0], bh[1]);
                mma_f16(acc[0][2 * j],     ah0, bl[0], bl[1]);
                mma_f16(acc[0][2 * j],     al0, bh[0], bh[1]);
                mma_f16(acc[1][2 * j],     ah1, bh[0], bh[1]);
                mma_f16(acc[1][2 * j],     ah1, bl[0], bl[1]);
                mma_f16(acc[1][2 * j],     al1, bh[0], bh[1]);
                mma_f16(acc[0][2 * j + 1], ah0, bh[2], bh[3]);
                mma_f16(acc[0][2 * j + 1], ah0, bl[2], bl[3]);
                mma_f16(acc[0][2 * j + 1], al0, bh[2], bh[3]);
                mma_f16(acc[1][2 * j + 1], ah1, bh[2], bh[3]);
                mma_f16(acc[1][2 * j + 1], ah1, bl[2], bl[3]);
                mma_f16(acc[1][2 * j + 1], al1, bh[2], bh[3]);
            }
        }

        if (pre) FO_STS_A((c + 2) % FG_STAGES);
        __syncthreads();
    }
#undef FO_LDG_A
#undef FO_STS_A
#undef FO_COPY_B

#pragma unroll
    for (int mt = 0; mt < 2; mt++) {
        const int row0 = m0 + wm * 32 + mt * 16 + g;
#pragma unroll
        for (int nt = 0; nt < 8; nt++) {
            const int col = wn * 64 + nt * 8 + tig * 2;
            const float bx = bias[col];
            const float by = bias[col + 1];
            float2 lo, hi;
            lo.x = acc[mt][nt][0] + bx;  lo.y = acc[mt][nt][1] + by;
            hi.x = acc[mt][nt][2] + bx;  hi.y = acc[mt][nt][3] + by;
            *reinterpret_cast<float2*>(&C[(size_t)row0 * N + col]) = lo;
            *reinterpret_cast<float2*>(&C[(size_t)(row0 + 8) * N + col]) = hi;
        }
    }
}

// ===========================================================================
// Unified prep kernel (unchanged).
// ===========================================================================
__global__ void prep_kernel(const float* __restrict__ W_v,
                            const float* __restrict__ W_out,
                            const float* __restrict__ W_off,
                            const float* __restrict__ W_aw,
                            const float* __restrict__ b_off,
                            const float* __restrict__ b_aw,
                            __half* __restrict__ wvt, __half* __restrict__ wot,
                            __half* __restrict__ wqt_hi, __half* __restrict__ wqt_lo,
                            float* __restrict__ bq)
{
    const int task = blockIdx.y;
    if (task < 2) {
        __shared__ float tile[32][33];
        const float* in = (task == 0) ? W_v : W_out;
        __half* out = (task == 0) ? wvt : wot;
        const int bx = (blockIdx.x & 15) * 32;
        const int by = (blockIdx.x >> 4) * 32;
#pragma unroll
        for (int j = 0; j < 32; j += 8)
            tile[threadIdx.y + j][threadIdx.x] =
                in[(size_t)(by + threadIdx.y + j) * DMODEL + bx + threadIdx.x];
        __syncthreads();
#pragma unroll
        for (int j = 0; j < 32; j += 8)
            out[(size_t)(bx + threadIdx.y + j) * DMODEL + by + threadIdx.x] =
                __float2half_rn(tile[threadIdx.x][threadIdx.y + j]);
    } else {
        const int tid = threadIdx.y * 32 + threadIdx.x;
        const int i = blockIdx.x * 256 + tid;
        if (i < 128 * DMODEL) {
            const int n = i / DMODEL;
            const int k = i - n * DMODEL;
            float w = 0.0f;
            if (n < 64)      w = W_off[k * 64 + n];
            else if (n < 96) w = W_aw[k * 32 + (n - 64)];
            const __half h = __float2half_rn(w);
            const __half l = __float2half_rn(w - __half2float(h));
            wqt_hi[i] = h;
            wqt_lo[i] = l;
        }
        if (i < 128) {
            float bv = 0.0f;
            if (i < 64)      bv = b_off[i];
            else if (i < 96) bv = b_aw[i - 64];
            bq[i] = bv;
        }
    }
}

// ===========================================================================
// Deformable sampling: 4 rows per block, 256 threads; uint4 taps.
// ===========================================================================
__global__ __launch_bounds__(256, 6) void deform_kernel(
    const __half* __restrict__ v,
    const float* __restrict__ offaw,
    __half* __restrict__ mid,
    int blkbase)
{
    __shared__ float s_w0[4][NHEAD][NPNT];
    __shared__ float s_w1[4][NHEAD][NPNT];
    __shared__ int   s_i0[4][NHEAD][NPNT];
    __shared__ int   s_i1[4][NHEAD][NPNT];

    const int blk0 = blkbase + blockIdx.x * 4;
    const int t = threadIdx.x;

    if (t < 32) {
        const int rr = t >> 3;
        const int h = t & 7;
        const int blk = blk0 + rr;
        const int l = blk & (LSEQ - 1);
        const float ref_y = (float)l / (float)(LSEQ - 1);
        const float* row = &offaw[(size_t)blk * 128];

        float lg[NPNT];
        float mx = -1e30f;
#pragma unroll
        for (int p = 0; p < NPNT; p++) {
            lg[p] = row[64 + h * NPNT + p];
            mx = fmaxf(mx, lg[p]);
        }
        float sum = 0.0f;
#pragma unroll
        for (int p = 0; p < NPNT; p++) { lg[p] = __expf(lg[p] - mx); sum += lg[p]; }
        const float inv = 1.0f / sum;

#pragma unroll
        for (int p = 0; p < NPNT; p++) {
            const float a = lg[p] * inv;
            const float ox = row[(h * NPNT + p) * 2 + 0];
            const float oy = row[(h * NPNT + p) * 2 + 1];
            const float locx = fminf(fmaxf(ox, 0.0f), 1.0f);
            const float locy = fminf(fmaxf(oy + ref_y, 0.0f), 1.0f);

            const float ix = ((locx + 1.0f) * (float)LSEQ - 1.0f) * 0.5f;
            const float iy = locy * 0.5f;
            const float ix0 = floorf(ix);
            const float fx = ix - ix0;
            const float iy0 = floorf(iy);
            const float fy = iy - iy0;
            const float ywt = (1.0f - fy) * (iy0 == 0.0f ? 1.0f : 0.0f)
                            + fy * ((iy0 + 1.0f) == 0.0f ? 1.0f : 0.0f);

            const int i0 = (int)ix0;
            const int i1 = i0 + 1;
            const float w = a * ywt;
            const bool v0 = (i0 >= 0) && (i0 < LSEQ);
            const bool v1 = (i1 >= 0) && (i1 < LSEQ);
            s_w0[rr][h][p] = v0 ? w * (1.0f - fx) : 0.0f;
            s_w1[rr][h][p] = v1 ? w * fx : 0.0f;
            s_i0[rr][h][p] = min(max(i0, 0), LSEQ - 1);
            s_i1[rr][h][p] = min(max(i1, 0), LSEQ - 1);
        }
    }
    __syncthreads();

    const int rr = t >> 6;
    const int u  = t & 63;
    const int h  = u >> 3;
    const int c8 = u & 7;
    const int blk = blk0 + rr;
    const int b = blk >> 11;

    const uint4* vb = reinterpret_cast<const uint4*>(
        v + (size_t)b * LSEQ * DMODEL + h * CHEAD) + c8;

    float a0 = 0.f, a1 = 0.f, a2 = 0.f, a3 = 0.f;
    float a4 = 0.f, a5 = 0.f, a6 = 0.f, a7 = 0.f;
#pragma unroll
    for (int p = 0; p < NPNT; p++) {
        const float w0 = s_w0[rr][h][p];
        const float w1 = s_w1[rr][h][p];
        const uint4 x0 = vb[(size_t)s_i0[rr][h][p] * (DMODEL / 8)];
        const uint4 x1 = vb[(size_t)s_i1[rr][h][p] * (DMODEL / 8)];
        const float2 f0a = __half22float2(*reinterpret_cast<const __half2*>(&x0.x));
        const float2 f0b = __half22float2(*reinterpret_cast<const __half2*>(&x0.y));
        const float2 f0c = __half22float2(*reinterpret_cast<const __half2*>(&x0.z));
        const float2 f0d = __half22float2(*reinterpret_cast<const __half2*>(&x0.w));
        const float2 f1a = __half22float2(*reinterpret_cast<const __half2*>(&x1.x));
        const float2 f1b = __half22float2(*reinterpret_cast<const __half2*>(&x1.y));
        const float2 f1c = __half22float2(*reinterpret_cast<const __half2*>(&x1.z));
        const float2 f1d = __half22float2(*reinterpret_cast<const __half2*>(&x1.w));
        a0 = fmaf(w0, f0a.x, a0); a1 = fmaf(w0, f0a.y, a1);
        a2 = fmaf(w0, f0b.x, a2); a3 = fmaf(w0, f0b.y, a3);
        a4 = fmaf(w0, f0c.x, a4); a5 = fmaf(w0, f0c.y, a5);
        a6 = fmaf(w0, f0d.x, a6); a7 = fmaf(w0, f0d.y, a7);
        a0 = fmaf(w1, f1a.x, a0); a1 = fmaf(w1, f1a.y, a1);
        a2 = fmaf(w1, f1b.x, a2); a3 = fmaf(w1, f1b.y, a3);
        a4 = fmaf(w1, f1c.x, a4); a5 = fmaf(w1, f1c.y, a5);
        a6 = fmaf(w1, f1d.x, a6); a7 = fmaf(w1, f1d.y, a7);
    }
    __half2 o0 = __floats2half2_rn(a0, a1);
    __half2 o1 = __floats2half2_rn(a2, a3);
    __half2 o2 = __floats2half2_rn(a4, a5);
    __half2 o3 = __floats2half2_rn(a6, a7);
    uint4 o;
    o.x = *reinterpret_cast<uint32_t*>(&o0);
    o.y = *reinterpret_cast<uint32_t*>(&o1);
    o.z = *reinterpret_cast<uint32_t*>(&o2);
    o.w = *reinterpret_cast<uint32_t*>(&o3);
    *reinterpret_cast<uint4*>(&mid[(size_t)blk * DMODEL + h * CHEAD + c8 * 8]) = o;
}

// ===========================================================================
// Host launch — round-14 schedule with 256-row-tile GEMMs.
//   s0: prep -> vG(h0) -> [wait offaw] deform(h0) -> out(h0) -> [wait s1]
//   s1: [wait prep] offaw(full) -> vG(h1) -> deform(h1) -> out(h1)
// ===========================================================================
extern "C" void kernel_launch(void* const* d_in, const int* in_sizes, int n_in,
                              void* d_out, int out_size)
{
    const float* query = (const float*)d_in[0];
    const float* value = (const float*)d_in[2];
    const float* W_v   = (const float*)d_in[3];
    const float* b_v   = (const float*)d_in[4];
    const float* W_off = (const float*)d_in[5];
    const float* b_off = (const float*)d_in[6];
    const float* W_aw  = (const float*)d_in[7];
    const float* b_aw  = (const float*)d_in[8];
    const float* W_out = (const float*)d_in[9];
    const float* b_out = (const float*)d_in[10];
    float* out = (float*)d_out;

    __half *pv, *pmid, *pwvt, *pwot, *pwqh, *pwql;
    float *poffaw, *pbq;
    cudaGetSymbolAddress((void**)&pv,     g_v);
    cudaGetSymbolAddress((void**)&pmid,   g_mid);
    cudaGetSymbolAddress((void**)&poffaw, g_offaw);
    cudaGetSymbolAddress((void**)&pwvt,   g_wvt);
    cudaGetSymbolAddress((void**)&pwot,   g_wot);
    cudaGetSymbolAddress((void**)&pwqh,   g_wqt_hi);
    cudaGetSymbolAddress((void**)&pwql,   g_wqt_lo);
    cudaGetSymbolAddress((void**)&pbq,    g_bq);

    cudaFuncSetAttribute((const void*)gemm_async_h256_kernel<float>,
                         cudaFuncAttributeMaxDynamicSharedMemorySize, BG_SMEM);
    cudaFuncSetAttribute((const void*)gemm_v256_kernel,
                         cudaFuncAttributeMaxDynamicSharedMemorySize, BG_SMEM);
    cudaFuncSetAttribute((const void*)gemm_offaw_fused_kernel,
                         cudaFuncAttributeMaxDynamicSharedMemorySize, FG_SMEM);

    const dim3 gemmGrid(DMODEL / 128, MHALF / 256);   // (4, 32) per half

    // --- s0: unified prep ---
    {
        dim3 tb(32, 8);
        dim3 tg(256, 3);
        prep_kernel<<<tg, tb>>>(W_v, W_out, W_off, W_aw, b_off, b_aw,
                                pwvt, pwot, pwqh, pwql, pbq);
    }
    cudaEventRecord(g_ev0, 0);
    cudaStreamWaitEvent(g_s1, g_ev0, 0);

    // --- s1: offaw (full M), then half-1 chain ---
    {
        dim3 grid(1, MROWS / 128);
        gemm_offaw_fused_kernel<<<grid, 256, FG_SMEM, g_s1>>>(
            query, pwqh, pwql, pbq, poffaw, 0, DMODEL);
    }
    cudaEventRecord(g_ev1, g_s1);
    gemm_v256_kernel<<<gemmGrid, 512, BG_SMEM, g_s1>>>(
        value, pwvt, b_v, pv, MHALF, DMODEL, DMODEL);
    deform_kernel<<<MHALF / 4, 256, 0, g_s1>>>(pv, poffaw, pmid, MHALF);
    gemm_async_h256_kernel<float><<<gemmGrid, 512, BG_SMEM, g_s1>>>(
        pmid, pwot, b_out, out, MHALF, DMODEL, DMODEL);
    cudaEventRecord(g_ev2, g_s1);

    // --- s0: half-0 chain ---
    gemm_v256_kernel<<<gemmGrid, 512, BG_SMEM>>>(
        value, pwvt, b_v, pv, 0, DMODEL, DMODEL);
    cudaStreamWaitEvent(0, g_ev1, 0);
    deform_kernel<<<MHALF / 4, 256>>>(pv, poffaw, pmid, 0);
    gemm_async_h256_kernel<float><<<gemmGrid, 512, BG_SMEM>>>(
        pmid, pwot, b_out, out, 0, DMODEL, DMODEL);

    // Join s1 back into the origin stream (required for capture).
    cudaStreamWaitEvent(0, g_ev2, 0);
}

// round 17
// speedup vs baseline: 1.0358x; 1.0358x over previous
#include <cuda_runtime.h>
#include <cuda_fp16.h>
#include <math.h>
#include <stdint.h>

// Problem constants
#define BATCH 8
#define LSEQ  2048
#define DMODEL 512
#define NHEAD 8
#define NPNT  4
#define CHEAD 64
#define MROWS (BATCH * LSEQ)   // 16384
#define MHALF (MROWS / 2)      // 8192

// Scratch (device globals; no allocation allowed)
__device__ __align__(16) __half g_v[MROWS * DMODEL];      // value projection (fp16)
__device__ __align__(16) __half g_mid[MROWS * DMODEL];    // deform output (fp16)
__device__ __align__(16) float  g_offaw[MROWS * 128];     // off(64)|aw(32)|pad, fp32
__device__ __align__(16) __half g_wvt[DMODEL * DMODEL];   // W_v^T   fp16 [N][K]
__device__ __align__(16) __half g_wot[DMODEL * DMODEL];   // W_out^T fp16 [N][K]
__device__ __align__(16) __half g_wqt_hi[128 * DMODEL];   // Wq^T hi fp16 [128][512]
__device__ __align__(16) __half g_wqt_lo[128 * DMODEL];   // Wq^T lo fp16
__device__ __align__(16) float  g_bq[128];

// Streams/events (created once at module load).
static cudaStream_t g_s1;
static cudaEvent_t g_ev0, g_ev1, g_ev2;
namespace {
struct StreamInit {
    StreamInit() {
        cudaStreamCreateWithFlags(&g_s1, cudaStreamNonBlocking);
        cudaEventCreateWithFlags(&g_ev0, cudaEventDisableTiming);
        cudaEventCreateWithFlags(&g_ev1, cudaEventDisableTiming);
        cudaEventCreateWithFlags(&g_ev2, cudaEventDisableTiming);
    }
};
StreamInit g_stream_init;
}

__device__ __forceinline__ uint32_t smem_u32(const void* p) {
    uint32_t a;
    asm("{ .reg .u64 t; cvta.to.shared.u64 t, %1; cvt.u32.u64 %0, t; }" : "=r"(a) : "l"(p));
    return a;
}

__device__ __forceinline__ void mma_f16(float c[4],
                                        const uint32_t a[4],
                                        uint32_t b0, uint32_t b1) {
    asm volatile(
        "mma.sync.aligned.m16n8k16.row.col.f32.f16.f16.f32 "
        "{%0,%1,%2,%3}, {%4,%5,%6,%7}, {%8,%9}, {%0,%1,%2,%3};"
        : "+f"(c[0]), "+f"(c[1]), "+f"(c[2]), "+f"(c[3])
        : "r"(a[0]), "r"(a[1]), "r"(a[2]), "r"(a[3]), "r"(b0), "r"(b1));
}

__device__ __forceinline__ void ldsm_x4(uint32_t r[4], uint32_t addr) {
    asm volatile(
        "ldmatrix.sync.aligned.m8n8.x4.shared.b16 {%0,%1,%2,%3}, [%4];"
        : "=r"(r[0]), "=r"(r[1]), "=r"(r[2]), "=r"(r[3]) : "r"(addr));
}

#define CP_ASYNC16(dst, src) \
    asm volatile("cp.async.cg.shared.global [%0], [%1], 16;" :: "r"(dst), "l"(src) : "memory")
#define CP_COMMIT() asm volatile("cp.async.commit_group;" ::: "memory")
#define CP_WAIT1()  asm volatile("cp.async.wait_group 1;" ::: "memory")
#define CP_WAIT2()  asm volatile("cp.async.wait_group 2;" ::: "memory")

// Common tile geometry (128x128, 2 CTA/SM — measured optimum)
#define HG_KC 32
#define HG_ROWB 80
#define HG_TILE (128 * HG_ROWB)
#define HG_STAGE (2 * HG_TILE)
#define HG_STAGES 4
#define HG_SMEM (HG_STAGES * HG_STAGE)  // 81920 B

// ===========================================================================
// Async fp16 GEMM (fp16 A): C[M,N] = A @ Bt^T + bias. (out-GEMM, fp32 out)
// ===========================================================================
template <typename OutT>
__global__ __launch_bounds__(256, 2)
void gemm_async_h_kernel(const __half* __restrict__ A, const __half* __restrict__ Bt,
                         const float* __restrict__ bias, OutT* __restrict__ C,
                         int mbase, int N, int K)
{
    extern __shared__ char smem[];
    const uint32_t sbase = smem_u32(smem);

    const int tid  = threadIdx.x;
    const int wid  = tid >> 5;
    const int lane = tid & 31;
    const int g    = lane >> 2;
    const int tig  = lane & 3;
    const int wm   = wid & 3;
    const int wn   = wid >> 2;

    const int m0 = mbase + blockIdx.y * 128;
    const int n0 = blockIdx.x * 128;

    const uint32_t aOff = (uint32_t)((wm * 32 + (lane & 15)) * HG_ROWB + (lane >> 4) * 16);
    const uint32_t bOff = (uint32_t)(HG_TILE +
        (wn * 64 + (lane & 7) + (lane >> 4) * 8) * HG_ROWB + ((lane >> 3) & 1) * 16);

    float acc[2][8][4];
#pragma unroll
    for (int mt = 0; mt < 2; mt++)
#pragma unroll
        for (int nt = 0; nt < 8; nt++)
#pragma unroll
            for (int j = 0; j < 4; j++) acc[mt][nt][j] = 0.0f;

    const int nch = K / HG_KC;

#define HCOPY_STAGE(s, chunk)                                                  \
    do {                                                                       \
        const int _k0 = (chunk) * HG_KC;                                       \
        const uint32_t _dA = sbase + (s) * HG_STAGE;                           \
        const uint32_t _dB = _dA + HG_TILE;                                    \
        _Pragma("unroll")                                                      \
        for (int e = 0; e < 2; e++) {                                          \
            const int cc = tid + e * 256;                                      \
            const int r = cc >> 2;                                             \
            const int q = cc & 3;                                              \
            CP_ASYNC16(_dA + r * HG_ROWB + q * 16,                             \
                       &A[(size_t)(m0 + r) * K + _k0 + q * 8]);                \
            CP_ASYNC16(_dB + r * HG_ROWB + q * 16,                             \
                       &Bt[(size_t)(n0 + r) * K + _k0 + q * 8]);               \
        }                                                                      \
    } while (0)

    HCOPY_STAGE(0, 0); CP_COMMIT();
    HCOPY_STAGE(1, 1); CP_COMMIT();
    HCOPY_STAGE(2, 2); CP_COMMIT();

    for (int c = 0; c < nch; ++c) {
        CP_WAIT2();
        __syncthreads();

        if (c + 3 < nch) {
            HCOPY_STAGE((c + 3) % HG_STAGES, c + 3);
        }
        CP_COMMIT();

        const uint32_t stageBase = sbase + (c % HG_STAGES) * HG_STAGE;
        const uint32_t aBase = stageBase + aOff;
        const uint32_t bBase = stageBase + bOff;

#pragma unroll
        for (int ks = 0; ks < 2; ks++) {
            uint32_t a0[4], a1[4];
            ldsm_x4(a0, aBase + ks * 32);
            ldsm_x4(a1, aBase + 16 * HG_ROWB + ks * 32);
#pragma unroll
            for (int j = 0; j < 4; j++) {
                uint32_t b[4];
                ldsm_x4(b, bBase + j * 16 * HG_ROWB + ks * 32);
                mma_f16(acc[0][2 * j],     a0, b[0], b[1]);
                mma_f16(acc[1][2 * j],     a1, b[0], b[1]);
                mma_f16(acc[0][2 * j + 1], a0, b[2], b[3]);
                mma_f16(acc[1][2 * j + 1], a1, b[2], b[3]);
            }
        }
        __syncthreads();
    }
#undef HCOPY_STAGE

#pragma unroll
    for (int mt = 0; mt < 2; mt++) {
        const int row0 = m0 + wm * 32 + mt * 16 + g;
#pragma unroll
        for (int nt = 0; nt < 8; nt++) {
            const int col = n0 + wn * 64 + nt * 8 + tig * 2;
            const float bx = bias[col];
            const float by = bias[col + 1];
            const float l0 = acc[mt][nt][0] + bx;
            const float l1 = acc[mt][nt][1] + by;
            const float h0 = acc[mt][nt][2] + bx;
            const float h1 = acc[mt][nt][3] + by;
            if constexpr (sizeof(OutT) == 2) {
                __half2* p0 = reinterpret_cast<__half2*>(&C[(size_t)row0 * N + col]);
                __half2* p1 = reinterpret_cast<__half2*>(&C[(size_t)(row0 + 8) * N + col]);
                *p0 = __floats2half2_rn(l0, l1);
                *p1 = __floats2half2_rn(h0, h1);
            } else {
                float2 lo, hi;
                lo.x = l0; lo.y = l1; hi.x = h0; hi.y = h1;
                *reinterpret_cast<float2*>(&C[(size_t)row0 * N + col]) = lo;
                *reinterpret_cast<float2*>(&C[(size_t)(row0 + 8) * N + col]) = hi;
            }
        }
    }
}

// ===========================================================================
// v-GEMM with fused fp32->fp16 A conversion. mbase: M-slice offset.
// ===========================================================================
__global__ __launch_bounds__(256, 2)
void gemm_v_f32a_kernel(const float* __restrict__ A, const __half* __restrict__ Bt,
                        const float* __restrict__ bias, __half* __restrict__ C,
                        int mbase, int N, int K)
{
    extern __shared__ char smem[];
    const uint32_t sbase = smem_u32(smem);

    const int tid  = threadIdx.x;
    const int wid  = tid >> 5;
    const int lane = tid & 31;
    const int g    = lane >> 2;
    const int tig  = lane & 3;
    const int wm   = wid & 3;
    const int wn   = wid >> 2;

    const int m0 = mbase + blockIdx.y * 128;
    const int n0 = blockIdx.x * 128;

    const uint32_t aOff = (uint32_t)((wm * 32 + (lane & 15)) * HG_ROWB + (lane >> 4) * 16);
    const uint32_t bOff = (uint32_t)(HG_TILE +
        (wn * 64 + (lane & 7) + (lane >> 4) * 8) * HG_ROWB + ((lane >> 3) & 1) * 16);

    float4 areg[2][2];

    float acc[2][8][4];
#pragma unroll
    for (int mt = 0; mt < 2; mt++)
#pragma unroll
        for (int nt = 0; nt < 8; nt++)
#pragma unroll
            for (int j = 0; j < 4; j++) acc[mt][nt][j] = 0.0f;

    const int nch = K / HG_KC;

#define VG_LDG_A(k0)                                                           \
    do {                                                                       \
        _Pragma("unroll")                                                      \
        for (int e = 0; e < 2; e++) {                                          \
            const int i = tid + e * 256;                                       \
            const int r = i >> 2;                                              \
            const int q2 = i & 3;                                              \
            const float* pA = &A[(size_t)(m0 + r) * K + (k0) + q2 * 8];        \
            areg[e][0] = *reinterpret_cast<const float4*>(pA);                 \
            areg[e][1] = *reinterpret_cast<const float4*>(pA + 4);             \
        }                                                                      \
    } while (0)

#define VG_STS_A(s)                                                            \
    do {                                                                       \
        _Pragma("unroll")                                                      \
        for (int e = 0; e < 2; e++) {                                          \
            const int i = tid + e * 256;                                       \
            const int r = i >> 2;                                              \
            const int q2 = i & 3;                                              \
            __half2 h0 = __floats2half2_rn(areg[e][0].x, areg[e][0].y);        \
            __half2 h1 = __floats2half2_rn(areg[e][0].z, areg[e][0].w);        \
            __half2 h2 = __floats2half2_rn(areg[e][1].x, areg[e][1].y);        \
            __half2 h3 = __floats2half2_rn(areg[e][1].z, areg[e][1].w);        \
            uint4 o;                                                           \
            o.x = *reinterpret_cast<uint32_t*>(&h0);                           \
            o.y = *reinterpret_cast<uint32_t*>(&h1);                           \
            o.z = *reinterpret_cast<uint32_t*>(&h2);                           \
            o.w = *reinterpret_cast<uint32_t*>(&h3);                           \
            *reinterpret_cast<uint4*>(                                         \
                smem + (s) * HG_STAGE + r * HG_ROWB + q2 * 16) = o;            \
        }                                                                      \
    } while (0)

#define VG_COPY_B(s, chunk)                                                    \
    do {                                                                       \
        const int _k0 = (chunk) * HG_KC;                                       \
        const uint32_t _dB = sbase + (s) * HG_STAGE + HG_TILE;                 \
        _Pragma("unroll")                                                      \
        for (int e = 0; e < 2; e++) {                                          \
            const int cc = tid + e * 256;                                      \
            const int r = cc >> 2;                                             \
            const int q = cc & 3;                                              \
            CP_ASYNC16(_dB + r * HG_ROWB + q * 16,                             \
                       &Bt[(size_t)(n0 + r) * K + _k0 + q * 8]);               \
        }                                                                      \
    } while (0)

    VG_LDG_A(0);          VG_STS_A(0);
    VG_LDG_A(HG_KC);      VG_STS_A(1);
    VG_LDG_A(2 * HG_KC);  VG_STS_A(2);
    VG_COPY_B(0, 0); CP_COMMIT();
    VG_COPY_B(1, 1); CP_COMMIT();
    VG_COPY_B(2, 2); CP_COMMIT();

    for (int c = 0; c < nch; ++c) {
        CP_WAIT2();
        __syncthreads();

        const bool pre = (c + 3) < nch;
        if (pre) {
            VG_LDG_A((c + 3) * HG_KC);
            VG_COPY_B((c + 3) % HG_STAGES, c + 3);
        }
        CP_COMMIT();

        const uint32_t stageBase = sbase + (c % HG_STAGES) * HG_STAGE;
        const uint32_t aBase = stageBase + aOff;
        const uint32_t bBase = stageBase + bOff;

#pragma unroll
        for (int ks = 0; ks < 2; ks++) {
            uint32_t a0[4], a1[4];
            ldsm_x4(a0, aBase + ks * 32);
            ldsm_x4(a1, aBase + 16 * HG_ROWB + ks * 32);
#pragma unroll
            for (int j = 0; j < 4; j++) {
                uint32_t b[4];
                ldsm_x4(b, bBase + j * 16 * HG_ROWB + ks * 32);
                mma_f16(acc[0][2 * j],     a0, b[0], b[1]);
                mma_f16(acc[1][2 * j],     a1, b[0], b[1]);
                mma_f16(acc[0][2 * j + 1], a0, b[2], b[3]);
                mma_f16(acc[1][2 * j + 1], a1, b[2], b[3]);
            }
        }

        if (pre) VG_STS_A((c + 3) % HG_STAGES);
        __syncthreads();
    }
#undef VG_LDG_A
#undef VG_STS_A
#undef VG_COPY_B

#pragma unroll
    for (int mt = 0; mt < 2; mt++) {
        const int row0 = m0 + wm * 32 + mt * 16 + g;
#pragma unroll
        for (int nt = 0; nt < 8; nt++) {
            const int col = n0 + wn * 64 + nt * 8 + tig * 2;
            const float bx = bias[col];
            const float by = bias[col + 1];
            __half2* p0 = reinterpret_cast<__half2*>(&C[(size_t)row0 * N + col]);
            __half2* p1 = reinterpret_cast<__half2*>(&C[(size_t)(row0 + 8) * N + col]);
            *p0 = __floats2half2_rn(acc[mt][nt][0] + bx, acc[mt][nt][1] + by);
            *p1 = __floats2half2_rn(acc[mt][nt][2] + bx, acc[mt][nt][3] + by);
        }
    }
}

// ===========================================================================
// Fused split-fp16 off/aw GEMM (in-kernel query split + ldmatrix).
// ===========================================================================
#define FG_TILE HG_TILE
#define FG_STAGE (4 * FG_TILE)
#define FG_STAGES 3
#define FG_SMEM (FG_STAGES * FG_STAGE)   // 122880 B

__global__ __launch_bounds__(256, 1)
void gemm_offaw_fused_kernel(const float* __restrict__ Q,
                             const __half* __restrict__ Bh, const __half* __restrict__ Bl,
                             const float* __restrict__ bias, float* __restrict__ C,
                             int mbase, int K)
{
    extern __shared__ char smem[];
    const uint32_t sbase = smem_u32(smem);
    const int N = 128;

    const int tid  = threadIdx.x;
    const int wid  = tid >> 5;
    const int lane = tid & 31;
    const int g    = lane >> 2;
    const int tig  = lane & 3;
    const int wm   = wid & 3;
    const int wn   = wid >> 2;

    const int m0 = mbase + blockIdx.y * 128;

    const uint32_t aOff = (uint32_t)((wm * 32 + (lane & 15)) * HG_ROWB + (lane >> 4) * 16);
    const uint32_t bOff = (uint32_t)(
        (wn * 64 + (lane & 7) + (lane >> 4) * 8) * HG_ROWB + ((lane >> 3) & 1) * 16);

    float4 areg[2][2];

    float acc[2][8][4];
#pragma unroll
    for (int mt = 0; mt < 2; mt++)
#pragma unroll
        for (int nt = 0; nt < 8; nt++)
#pragma unroll
            for (int j = 0; j < 4; j++) acc[mt][nt][j] = 0.0f;

    const int nch = K / HG_KC;

#define FO_LDG_A(k0)                                                           \
    do {                                                                       \
        _Pragma("unroll")                                                      \
        for (int e = 0; e < 2; e++) {                                          \
            const int i = tid + e * 256;                                       \
            const int r = i >> 2;                                              \
            const int q2 = i & 3;                                              \
            const float* pQ = &Q[(size_t)(m0 + r) * K + (k0) + q2 * 8];        \
            areg[e][0] = *reinterpret_cast<const float4*>(pQ);                 \
            areg[e][1] = *reinterpret_cast<const float4*>(pQ + 4);             \
        }                                                                      \
    } while (0)

#define FO_STS_A(s)                                                            \
    do {                                                                       \
        _Pragma("unroll")                                                      \
        for (int e = 0; e < 2; e++) {                                          \
            const int i = tid + e * 256;                                       \
            const int r = i >> 2;                                              \
            const int q2 = i & 3;                                              \
            const uint32_t od = (s) * FG_STAGE + r * HG_ROWB + q2 * 16;        \
            float hf[8], lf[8];                                                \
            const float* av = reinterpret_cast<const float*>(areg[e]);         \
            _Pragma("unroll")                                                  \
            for (int x = 0; x < 8; x++) {                                      \
                const __half hh = __float2half_rn(av[x]);                      \
                hf[x] = __half2float(hh);                                      \
                lf[x] = av[x] - hf[x];                                         \
            }                                                                  \
            __half2 H[4], L[4];                                                \
            _Pragma("unroll")                                                  \
            for (int x = 0; x < 4; x++) {                                      \
                H[x] = __floats2half2_rn(hf[2 * x], hf[2 * x + 1]);            \
                L[x] = __floats2half2_rn(lf[2 * x], lf[2 * x + 1]);            \
            }                                                                  \
            uint4 oh, ol;                                                      \
            oh.x = *reinterpret_cast<uint32_t*>(&H[0]);                        \
            oh.y = *reinterpret_cast<uint32_t*>(&H[1]);                        \
            oh.z = *reinterpret_cast<uint32_t*>(&H[2]);                        \
            oh.w = *reinterpret_cast<uint32_t*>(&H[3]);                        \
            ol.x = *reinterpret_cast<uint32_t*>(&L[0]);                        \
            ol.y = *reinterpret_cast<uint32_t*>(&L[1]);                        \
            ol.z = *reinterpret_cast<uint32_t*>(&L[2]);                        \
            ol.w = *reinterpret_cast<uint32_t*>(&L[3]);                        \
            *reinterpret_cast<uint4*>(smem + od) = oh;                         \
            *reinterpret_cast<uint4*>(smem + FG_TILE + od) = ol;               \
        }                                                                      \
    } while (0)

#define FO_COPY_B(s, chunk)                                                    \
    do {                                                                       \
        const int _k0 = (chunk) * HG_KC;                                       \
        const uint32_t _d0 = sbase + (s) * FG_STAGE;                           \
        _Pragma("unroll")                                                      \
        for (int e = 0; e < 2; e++) {                                          \
            const int cc = tid + e * 256;                                      \
            const int r = cc >> 2;                                             \
            const int q = cc & 3;                                              \
            const uint32_t od = r * HG_ROWB + q * 16;                          \
            const size_t ob = (size_t)r * K + _k0 + q * 8;                     \
            CP_ASYNC16(_d0 + 2 * FG_TILE + od, &Bh[ob]);                       \
            CP_ASYNC16(_d0 + 3 * FG_TILE + od, &Bl[ob]);                       \
        }                                                                      \
    } while (0)

    FO_LDG_A(0);      FO_STS_A(0);
    FO_LDG_A(HG_KC);  FO_STS_A(1);
    FO_COPY_B(0, 0); CP_COMMIT();
    FO_COPY_B(1, 1); CP_COMMIT();

    for (int c = 0; c < nch; ++c) {
        CP_WAIT1();
        __syncthreads();

        const bool pre = (c + 2) < nch;
        if (pre) {
            FO_LDG_A((c + 2) * HG_KC);
            FO_COPY_B((c + 2) % FG_STAGES, c + 2);
        }
        CP_COMMIT();

        const uint32_t stageBase = sbase + (c % FG_STAGES) * FG_STAGE;
        const uint32_t ahBase = stageBase + aOff;
        const uint32_t alBase = ahBase + FG_TILE;
        const uint32_t bhBase = stageBase + 2 * FG_TILE + bOff;
        const uint32_t blBase = bhBase + FG_TILE;

#pragma unroll
        for (int ks = 0; ks < 2; ks++) {
            uint32_t ah0[4], ah1[4], al0[4], al1[4];
            ldsm_x4(ah0, ahBase + ks * 32);
            ldsm_x4(ah1, ahBase + 16 * HG_ROWB + ks * 32);
            ldsm_x4(al0, alBase + ks * 32);
            ldsm_x4(al1, alBase + 16 * HG_ROWB + ks * 32);
#pragma unroll
            for (int j = 0; j < 4; j++) {
                uint32_t bh[4], bl[4];
                ldsm_x4(bh, bhBase + j * 16 * HG_ROWB + ks * 32);
                ldsm_x4(bl, blBase + j * 16 * HG_ROWB + ks * 32);
                mma_f16(acc[0][2 * j],     ah0, bh[0], bh[1]);
                mma_f16(acc[0][2 * j],     ah0, bl[0], bl[1]);
                mma_f16(acc[0][2 * j],     al0, bh[0], bh[1]);
                mma_f16(acc[1][2 * j],     ah1, bh[0], bh[1]);
                mma_f16(acc[1][2 * j],     ah1, bl[0], bl[1]);
                mma_f16(acc[1][2 * j],     al1, bh[0], bh[1]);
                mma_f16(acc[0][2 * j + 1], ah0, bh[2], bh[3]);
                mma_f16(acc[0][2 * j + 1], ah0, bl[2], bl[3]);
                mma_f16(acc[0][2 * j + 1], al0, bh[2], bh[3]);
                mma_f16(acc[1][2 * j + 1], ah1, bh[2], bh[3]);
                mma_f16(acc[1][2 * j + 1], ah1, bl[2], bl[3]);
                mma_f16(acc[1][2 * j + 1], al1, bh[2], bh[3]);
            }
        }

        if (pre) FO_STS_A((c + 2) % FG_STAGES);
        __syncthreads();
    }
#undef FO_LDG_A
#undef FO_STS_A
#undef FO_COPY_B

#pragma unroll
    for (int mt = 0; mt < 2; mt++) {
        const int row0 = m0 + wm * 32 + mt * 16 + g;
#pragma unroll
        for (int nt = 0; nt < 8; nt++) {
            const int col = wn * 64 + nt * 8 + tig * 2;
            const float bx = bias[col];
            const float by = bias[col + 1];
            float2 lo, hi;
            lo.x = acc[mt][nt][0] + bx;  lo.y = acc[mt][nt][1] + by;
            hi.x = acc[mt][nt][2] + bx;  hi.y = acc[mt][nt][3] + by;
            *reinterpret_cast<float2*>(&C[(size_t)row0 * N + col]) = lo;
            *reinterpret_cast<float2*>(&C[(size_t)(row0 + 8) * N + col]) = hi;
        }
    }
}

// ===========================================================================
// Unified prep kernel.
// ===========================================================================
__global__ void prep_kernel(const float* __restrict__ W_v,
                            const float* __restrict__ W_out,
                            const float* __restrict__ W_off,
                            const float* __restrict__ W_aw,
                            const float* __restrict__ b_off,
                            const float* __restrict__ b_aw,
                            __half* __restrict__ wvt, __half* __restrict__ wot,
                            __half* __restrict__ wqt_hi, __half* __restrict__ wqt_lo,
                            float* __restrict__ bq)
{
    const int task = blockIdx.y;
    if (task < 2) {
        __shared__ float tile[32][33];
        const float* in = (task == 0) ? W_v : W_out;
        __half* out = (task == 0) ? wvt : wot;
        const int bx = (blockIdx.x & 15) * 32;
        const int by = (blockIdx.x >> 4) * 32;
#pragma unroll
        for (int j = 0; j < 32; j += 8)
            tile[threadIdx.y + j][threadIdx.x] =
                in[(size_t)(by + threadIdx.y + j) * DMODEL + bx + threadIdx.x];
        __syncthreads();
#pragma unroll
        for (int j = 0; j < 32; j += 8)
            out[(size_t)(bx + threadIdx.y + j) * DMODEL + by + threadIdx.x] =
                __float2half_rn(tile[threadIdx.x][threadIdx.y + j]);
    } else {
        const int tid = threadIdx.y * 32 + threadIdx.x;
        const int i = blockIdx.x * 256 + tid;
        if (i < 128 * DMODEL) {
            const int n = i / DMODEL;
            const int k = i - n * DMODEL;
            float w = 0.0f;
            if (n < 64)      w = W_off[k * 64 + n];
            else if (n < 96) w = W_aw[k * 32 + (n - 64)];
            const __half h = __float2half_rn(w);
            const __half l = __float2half_rn(w - __half2float(h));
            wqt_hi[i] = h;
            wqt_lo[i] = l;
        }
        if (i < 128) {
            float bv = 0.0f;
            if (i < 64)      bv = b_off[i];
            else if (i < 96) bv = b_aw[i - 64];
            bq[i] = bv;
        }
    }
}

// ===========================================================================
// Deformable sampling: 4 rows per block, 256 threads; uint4 taps.
// ===========================================================================
__global__ __launch_bounds__(256, 6) void deform_kernel(
    const __half* __restrict__ v,
    const float* __restrict__ offaw,
    __half* __restrict__ mid,
    int blkbase)
{
    __shared__ float s_w0[4][NHEAD][NPNT];
    __shared__ float s_w1[4][NHEAD][NPNT];
    __shared__ int   s_i0[4][NHEAD][NPNT];
    __shared__ int   s_i1[4][NHEAD][NPNT];

    const int blk0 = blkbase + blockIdx.x * 4;
    const int t = threadIdx.x;

    if (t < 32) {
        const int rr = t >> 3;
        const int h = t & 7;
        const int blk = blk0 + rr;
        const int l = blk & (LSEQ - 1);
        const float ref_y = (float)l / (float)(LSEQ - 1);
        const float* row = &offaw[(size_t)blk * 128];

        float lg[NPNT];
        float mx = -1e30f;
#pragma unroll
        for (int p = 0; p < NPNT; p++) {
            lg[p] = row[64 + h * NPNT + p];
            mx = fmaxf(mx, lg[p]);
        }
        float sum = 0.0f;
#pragma unroll
        for (int p = 0; p < NPNT; p++) { lg[p] = __expf(lg[p] - mx); sum += lg[p]; }
        const float inv = 1.0f / sum;

#pragma unroll
        for (int p = 0; p < NPNT; p++) {
            const float a = lg[p] * inv;
            const float ox = row[(h * NPNT + p) * 2 + 0];
            const float oy = row[(h * NPNT + p) * 2 + 1];
            const float locx = fminf(fmaxf(ox, 0.0f), 1.0f);
            const float locy = fminf(fmaxf(oy + ref_y, 0.0f), 1.0f);

            const float ix = ((locx + 1.0f) * (float)LSEQ - 1.0f) * 0.5f;
            const float iy = locy * 0.5f;
            const float ix0 = floorf(ix);
            const float fx = ix - ix0;
            const float iy0 = floorf(iy);
            const float fy = iy - iy0;
            const float ywt = (1.0f - fy) * (iy0 == 0.0f ? 1.0f : 0.0f)
                            + fy * ((iy0 + 1.0f) == 0.0f ? 1.0f : 0.0f);

            const int i0 = (int)ix0;
            const int i1 = i0 + 1;
            const float w = a * ywt;
            const bool v0 = (i0 >= 0) && (i0 < LSEQ);
            const bool v1 = (i1 >= 0) && (i1 < LSEQ);
            s_w0[rr][h][p] = v0 ? w * (1.0f - fx) : 0.0f;
            s_w1[rr][h][p] = v1 ? w * fx : 0.0f;
            s_i0[rr][h][p] = min(max(i0, 0), LSEQ - 1);
            s_i1[rr][h][p] = min(max(i1, 0), LSEQ - 1);
        }
    }
    __syncthreads();

    const int rr = t >> 6;
    const int u  = t & 63;
    const int h  = u >> 3;
    const int c8 = u & 7;
    const int blk = blk0 + rr;
    const int b = blk >> 11;

    const uint4* vb = reinterpret_cast<const uint4*>(
        v + (size_t)b * LSEQ * DMODEL + h * CHEAD) + c8;

    float a0 = 0.f, a1 = 0.f, a2 = 0.f, a3 = 0.f;
    float a4 = 0.f, a5 = 0.f, a6 = 0.f, a7 = 0.f;
#pragma unroll
    for (int p = 0; p < NPNT; p++) {
        const float w0 = s_w0[rr][h][p];
        const float w1 = s_w1[rr][h][p];
        const uint4 x0 = vb[(size_t)s_i0[rr][h][p] * (DMODEL / 8)];
        const uint4 x1 = vb[(size_t)s_i1[rr][h][p] * (DMODEL / 8)];
        const float2 f0a = __half22float2(*reinterpret_cast<const __half2*>(&x0.x));
        const float2 f0b = __half22float2(*reinterpret_cast<const __half2*>(&x0.y));
        const float2 f0c = __half22float2(*reinterpret_cast<const __half2*>(&x0.z));
        const float2 f0d = __half22float2(*reinterpret_cast<const __half2*>(&x0.w));
        const float2 f1a = __half22float2(*reinterpret_cast<const __half2*>(&x1.x));
        const float2 f1b = __half22float2(*reinterpret_cast<const __half2*>(&x1.y));
        const float2 f1c = __half22float2(*reinterpret_cast<const __half2*>(&x1.z));
        const float2 f1d = __half22float2(*reinterpret_cast<const __half2*>(&x1.w));
        a0 = fmaf(w0, f0a.x, a0); a1 = fmaf(w0, f0a.y, a1);
        a2 = fmaf(w0, f0b.x, a2); a3 = fmaf(w0, f0b.y, a3);
        a4 = fmaf(w0, f0c.x, a4); a5 = fmaf(w0, f0c.y, a5);
        a6 = fmaf(w0, f0d.x, a6); a7 = fmaf(w0, f0d.y, a7);
        a0 = fmaf(w1, f1a.x, a0); a1 = fmaf(w1, f1a.y, a1);
        a2 = fmaf(w1, f1b.x, a2); a3 = fmaf(w1, f1b.y, a3);
        a4 = fmaf(w1, f1c.x, a4); a5 = fmaf(w1, f1c.y, a5);
        a6 = fmaf(w1, f1d.x, a6); a7 = fmaf(w1, f1d.y, a7);
    }
    __half2 o0 = __floats2half2_rn(a0, a1);
    __half2 o1 = __floats2half2_rn(a2, a3);
    __half2 o2 = __floats2half2_rn(a4, a5);
    __half2 o3 = __floats2half2_rn(a6, a7);
    uint4 o;
    o.x = *reinterpret_cast<uint32_t*>(&o0);
    o.y = *reinterpret_cast<uint32_t*>(&o1);
    o.z = *reinterpret_cast<uint32_t*>(&o2);
    o.w = *reinterpret_cast<uint32_t*>(&o3);
    *reinterpret_cast<uint4*>(&mid[(size_t)blk * DMODEL + h * CHEAD + c8 * 8]) = o;
}

// ===========================================================================
// Host launch — round-14 schedule (measured optimum).
//   s0: prep -> vG(h0) -> [wait offaw] deform(h0) -> out(h0) -> [wait s1]
//   s1: [wait prep] offaw(full) -> vG(h1) -> deform(h1) -> out(h1)
// ===========================================================================
extern "C" void kernel_launch(void* const* d_in, const int* in_sizes, int n_in,
                              void* d_out, int out_size)
{
    const float* query = (const float*)d_in[0];
    const float* value = (const float*)d_in[2];
    const float* W_v   = (const float*)d_in[3];
    const float* b_v   = (const float*)d_in[4];
    const float* W_off = (const float*)d_in[5];
    const float* b_off = (const float*)d_in[6];
    const float* W_aw  = (const float*)d_in[7];
    const float* b_aw  = (const float*)d_in[8];
    const float* W_out = (const float*)d_in[9];
    const float* b_out = (const float*)d_in[10];
    float* out = (float*)d_out;

    __half *pv, *pmid, *pwvt, *pwot, *pwqh, *pwql;
    float *poffaw, *pbq;
    cudaGetSymbolAddress((void**)&pv,     g_v);
    cudaGetSymbolAddress((void**)&pmid,   g_mid);
    cudaGetSymbolAddress((void**)&poffaw, g_offaw);
    cudaGetSymbolAddress((void**)&pwvt,   g_wvt);
    cudaGetSymbolAddress((void**)&pwot,   g_wot);
    cudaGetSymbolAddress((void**)&pwqh,   g_wqt_hi);
    cudaGetSymbolAddress((void**)&pwql,   g_wqt_lo);
    cudaGetSymbolAddress((void**)&pbq,    g_bq);

    cudaFuncSetAttribute((const void*)gemm_async_h_kernel<float>,
                         cudaFuncAttributeMaxDynamicSharedMemorySize, HG_SMEM);
    cudaFuncSetAttribute((const void*)gemm_v_f32a_kernel,
                         cudaFuncAttributeMaxDynamicSharedMemorySize, HG_SMEM);
    cudaFuncSetAttribute((const void*)gemm_offaw_fused_kernel,
                         cudaFuncAttributeMaxDynamicSharedMemorySize, FG_SMEM);

    const dim3 gemmGrid(DMODEL / 128, MHALF / 128);   // (4, 64) per half

    // --- s0: unified prep ---
    {
        dim3 tb(32, 8);
        dim3 tg(256, 3);
        prep_kernel<<<tg, tb>>>(W_v, W_out, W_off, W_aw, b_off, b_aw,
                                pwvt, pwot, pwqh, pwql, pbq);
    }
    cudaEventRecord(g_ev0, 0);
    cudaStreamWaitEvent(g_s1, g_ev0, 0);

    // --- s1: offaw (full M), then half-1 chain ---
    {
        dim3 grid(1, MROWS / 128);
        gemm_offaw_fused_kernel<<<grid, 256, FG_SMEM, g_s1>>>(
            query, pwqh, pwql, pbq, poffaw, 0, DMODEL);
    }
    cudaEventRecord(g_ev1, g_s1);   // offaw done (needed by s0's deform h0)
    gemm_v_f32a_kernel<<<gemmGrid, 256, HG_SMEM, g_s1>>>(
        value, pwvt, b_v, pv, MHALF, DMODEL, DMODEL);
    deform_kernel<<<MHALF / 4, 256, 0, g_s1>>>(pv, poffaw, pmid, MHALF);
    gemm_async_h_kernel<float><<<gemmGrid, 256, HG_SMEM, g_s1>>>(
        pmid, pwot, b_out, out, MHALF, DMODEL, DMODEL);
    cudaEventRecord(g_ev2, g_s1);   // s1 tail

    // --- s0: half-0 chain ---
    gemm_v_f32a_kernel<<<gemmGrid, 256, HG_SMEM>>>(
        value, pwvt, b_v, pv, 0, DMODEL, DMODEL);
    cudaStreamWaitEvent(0, g_ev1, 0);
    deform_kernel<<<MHALF / 4, 256>>>(pv, poffaw, pmid, 0);
    gemm_async_h_kernel<float><<<gemmGrid, 256, HG_SMEM>>>(
        pmid, pwot, b_out, out, 0, DMODEL, DMODEL);

    // Join s1 back into the origin stream (required for capture).
    cudaStreamWaitEvent(0, g_ev2, 0);
}